// round 8
// baseline (speedup 1.0000x reference)
#include <cuda_runtime.h>

// ---------------------------------------------------------------------------
// SimpleRNN: x[128,1024,256], W_i2h[512,768] (=[Wx|Wh]), b_i2h[512],
//            W_h2o[256,512], b_h2o[256]
// out = concat( outputs[128,1024,256], h_last[128,512] ), fp32
//
// Phase 1: xW[t][b][h] = x[b,t,:]·Wx[h,:] + b_i2h[h]        (tiled fp32 GEMM)
// Phase 2: persistent scan, 128 CTAs = 8 batch-groups x 16 hid-groups,
//          Wh slice register-resident, counter-based group sync per step
// Phase 3: out[b][s][o] = hs[s][b][:]·W_h2o[o,:] + b_h2o[o] (tiled fp32 GEMM)
// ---------------------------------------------------------------------------

namespace {
constexpr int B_ = 128;   // batch
constexpr int S_ = 1024;  // seq
constexpr int I_ = 256;   // in
constexpr int H_ = 512;   // hid
constexpr int O_ = 256;   // out
constexpr int BG = 8;     // batch groups
constexpr int JG = 16;    // hid groups (CTAs per batch group)
constexpr int BSL = B_ / BG;  // 16 batch rows per group
}

// Scratch (allocation-free rule: __device__ globals)
__device__ float    g_xw[(size_t)S_ * B_ * H_];   // 256 MB, [t][b][h]
__device__ float    g_hs[(size_t)S_ * B_ * H_];   // 256 MB, [t][b][h]
__device__ unsigned g_cnt[BG * S_];

// ---------------------------------------------------------------------------
__global__ void zero_cnt_kernel() {
    int i = blockIdx.x * blockDim.x + threadIdx.x;
    if (i < BG * S_) g_cnt[i] = 0u;
}

// ---------------------------------------------------------------------------
// Generic C[r][c] = sum_k A'[r][k]*B[c][k] + bias[c]
// Row r decomposes as r = hi*D? no: hi = r/D, lo = r%D; A row offset =
// (lo*SWAP + hi)*K   (handles both x's [b][t][i] and hs's [t][b][h] layouts).
template<int K, int N, int BSTR, int D, int SWAP>
__global__ void __launch_bounds__(256) gemm_bias_kernel(
    const float* __restrict__ A, const float* __restrict__ Bm,
    const float* __restrict__ bias, float* __restrict__ C)
{
    __shared__ float As[16][64];
    __shared__ float Bs[16][64];
    const int tid  = threadIdx.x;
    const int r0   = blockIdx.y * 64;
    const int c0   = blockIdx.x * 64;
    const int lrow = tid >> 2;          // 0..63
    const int lk4  = (tid & 3) << 2;    // 0,4,8,12

    const int r  = r0 + lrow;
    const int hi = r / D, lo = r % D;
    const float* Arow = A  + ((size_t)lo * SWAP + hi) * K;
    const float* Brow = Bm + (size_t)(c0 + lrow) * BSTR;

    const int tr = tid >> 4, tc = tid & 15;   // 16x16 threads, 4x4 micro-tile
    float acc[4][4] = {};

    float4 av = *reinterpret_cast<const float4*>(Arow + lk4);
    float4 bv = *reinterpret_cast<const float4*>(Brow + lk4);

    for (int kc = 0; kc < K; kc += 16) {
        __syncthreads();
        As[lk4+0][lrow]=av.x; As[lk4+1][lrow]=av.y; As[lk4+2][lrow]=av.z; As[lk4+3][lrow]=av.w;
        Bs[lk4+0][lrow]=bv.x; Bs[lk4+1][lrow]=bv.y; Bs[lk4+2][lrow]=bv.z; Bs[lk4+3][lrow]=bv.w;
        __syncthreads();
        if (kc + 16 < K) {  // prefetch next chunk while computing this one
            av = *reinterpret_cast<const float4*>(Arow + kc + 16 + lk4);
            bv = *reinterpret_cast<const float4*>(Brow + kc + 16 + lk4);
        }
#pragma unroll
        for (int kk = 0; kk < 16; ++kk) {
            float4 a = *reinterpret_cast<const float4*>(&As[kk][tr * 4]);
            float4 b = *reinterpret_cast<const float4*>(&Bs[kk][tc * 4]);
            float aa[4] = {a.x, a.y, a.z, a.w};
            float bb[4] = {b.x, b.y, b.z, b.w};
#pragma unroll
            for (int i = 0; i < 4; ++i)
#pragma unroll
                for (int j = 0; j < 4; ++j)
                    acc[i][j] = fmaf(aa[i], bb[j], acc[i][j]);
        }
    }

    float4 bsv = *reinterpret_cast<const float4*>(bias + c0 + tc * 4);
#pragma unroll
    for (int i = 0; i < 4; ++i) {
        float4 v;
        v.x = acc[i][0] + bsv.x;
        v.y = acc[i][1] + bsv.y;
        v.z = acc[i][2] + bsv.z;
        v.w = acc[i][3] + bsv.w;
        *reinterpret_cast<float4*>(C + (size_t)(r0 + tr * 4 + i) * N + c0 + tc * 4) = v;
    }
}

// ---------------------------------------------------------------------------
// Persistent scan. Grid (JG, BG) = (16, 8) CTAs, 256 threads each.
// CTA (jg,bg): hid slice [jg*32, jg*32+32), batch slice [bg*16, bg*16+16).
// Warp w handles 4 hid outputs; lane holds Wh[j][lane + 32*i], i=0..15 in regs.
__global__ void __launch_bounds__(256, 1) rnn_scan_kernel(const float* __restrict__ W)
{
    const int jg   = blockIdx.x;   // 0..15
    const int bg   = blockIdx.y;   // 0..7
    const int tid  = threadIdx.x;
    const int warp = tid >> 5;
    const int lane = tid & 31;
    const int jbase = jg * 32 + warp * 4;

    __shared__ float hsm[BSL * H_];   // 32 KB: h_{t-1} for this batch group

    // Register-resident Wh slice: Wh[j][k] = W[j*(I_+H_) + I_ + k]
    float w0[16], w1[16], w2[16], w3[16];
#pragma unroll
    for (int i = 0; i < 16; ++i) {
        int k = lane + 32 * i;
        w0[i] = W[(size_t)(jbase + 0) * (I_ + H_) + I_ + k];
        w1[i] = W[(size_t)(jbase + 1) * (I_ + H_) + I_ + k];
        w2[i] = W[(size_t)(jbase + 2) * (I_ + H_) + I_ + k];
        w3[i] = W[(size_t)(jbase + 3) * (I_ + H_) + I_ + k];
    }

    unsigned* cnt = g_cnt + bg * S_;

    for (int t = 0; t < S_; ++t) {
        if (t > 0) {
            // acquire: wait until all 16 CTAs of this batch group finished t-1
            if (tid == 0) {
                unsigned v;
                do {
                    asm volatile("ld.relaxed.gpu.global.u32 %0, [%1];"
                                 : "=r"(v) : "l"(cnt + (t - 1)) : "memory");
                } while (v < (unsigned)JG);
                asm volatile("fence.acq_rel.gpu;" ::: "memory");
            }
            __syncthreads();
            // stage h_{t-1} rows for our batch slice into smem (contiguous 32KB)
            const float4* src = reinterpret_cast<const float4*>(
                g_hs + ((size_t)(t - 1) * B_ + bg * BSL) * H_);
            float4* dst = reinterpret_cast<float4*>(hsm);
#pragma unroll
            for (int i = 0; i < (BSL * H_ / 4) / 256; ++i)
                dst[tid + 256 * i] = src[tid + 256 * i];
            __syncthreads();
        }

        float*       outrow = g_hs + ((size_t)t * B_ + bg * BSL) * H_;
        const float* xwrow  = g_xw + ((size_t)t * B_ + bg * BSL) * H_;

        for (int b = 0; b < BSL; ++b) {
            float a0 = 0.f, a1 = 0.f, a2 = 0.f, a3 = 0.f;
            if (t > 0) {
                const float* hrow = hsm + b * H_;
#pragma unroll
                for (int i = 0; i < 16; ++i) {
                    float hv = hrow[lane + 32 * i];     // conflict-free LDS
                    a0 = fmaf(hv, w0[i], a0);
                    a1 = fmaf(hv, w1[i], a1);
                    a2 = fmaf(hv, w2[i], a2);
                    a3 = fmaf(hv, w3[i], a3);
                }
#pragma unroll
                for (int off = 16; off; off >>= 1) {
                    a0 += __shfl_xor_sync(0xffffffffu, a0, off);
                    a1 += __shfl_xor_sync(0xffffffffu, a1, off);
                    a2 += __shfl_xor_sync(0xffffffffu, a2, off);
                    a3 += __shfl_xor_sync(0xffffffffu, a3, off);
                }
            }
            if (lane < 4) {
                float s  = (lane == 0) ? a0 : (lane == 1) ? a1 : (lane == 2) ? a2 : a3;
                float xv = xwrow[b * H_ + jbase + lane];
                outrow[b * H_ + jbase + lane] = tanhf(xv + s);
            }
        }
        __syncthreads();
        // release: publish our hid slice of h_t
        if (tid == 0) {
            asm volatile("fence.acq_rel.gpu;" ::: "memory");
            atomicAdd(cnt + t, 1u);
        }
    }
}

// ---------------------------------------------------------------------------
__global__ void copy_hlast_kernel(float* __restrict__ out) {
    int i = blockIdx.x * blockDim.x + threadIdx.x;
    out[i] = g_hs[(size_t)(S_ - 1) * B_ * H_ + i];   // [b][h] slice, contiguous
}

// ---------------------------------------------------------------------------
extern "C" void kernel_launch(void* const* d_in, const int* in_sizes, int n_in,
                              void* d_out, int out_size)
{
    const float* x  = (const float*)d_in[0];   // [128,1024,256]
    const float* Wi = (const float*)d_in[1];   // [512,768]
    const float* bi = (const float*)d_in[2];   // [512]
    const float* Wo = (const float*)d_in[3];   // [256,512]
    const float* bo = (const float*)d_in[4];   // [256]
    float* out = (float*)d_out;

    float* xw_d = nullptr;
    float* hs_d = nullptr;
    cudaGetSymbolAddress((void**)&xw_d, g_xw);
    cudaGetSymbolAddress((void**)&hs_d, g_hs);

    // reset sync counters (graph replays must be deterministic)
    zero_cnt_kernel<<<(BG * S_ + 255) / 256, 256>>>();

    // Phase 1: xW[t][b][h]  (r = t*128+b, A row = (b*S_+t)*I_)
    {
        dim3 g(H_ / 64, (S_ * B_) / 64);
        gemm_bias_kernel<I_, H_, I_ + H_, B_, S_><<<g, 256>>>(x, Wi, bi, xw_d);
    }

    // Phase 2: sequential scan (persistent, 128 co-resident CTAs)
    rnn_scan_kernel<<<dim3(JG, BG), 256>>>(Wi);

    // Phase 3: outputs[b][s][o]  (r = b*S_+s, A row = (s*B_+b)*H_)
    {
        dim3 g(O_ / 64, (B_ * S_) / 64);
        gemm_bias_kernel<H_, O_, H_, S_, B_><<<g, 256>>>(hs_d, Wo, bo, out);
    }

    // h_last
    if (out_size >= B_ * S_ * O_ + B_ * H_)
        copy_hlast_kernel<<<(B_ * H_) / 256, 256>>>(out + (size_t)B_ * S_ * O_);
}

// round 10
// speedup vs baseline: 2.5980x; 2.5980x over previous
#include <cuda_runtime.h>

// ---------------------------------------------------------------------------
// SimpleRNN: x[128,1024,256], W_i2h[512,768] (=[Wx|Wh]), b_i2h[512],
//            W_h2o[256,512], b_h2o[256]
// out = concat( outputs[128,1024,256], h_last[128,512] ), fp32
// ---------------------------------------------------------------------------

namespace {
constexpr int B_ = 128;   // batch
constexpr int S_ = 1024;  // seq
constexpr int I_ = 256;   // in
constexpr int H_ = 512;   // hid
constexpr int O_ = 256;   // out
constexpr int BG = 8;     // batch groups
constexpr int JG = 16;    // hid groups (CTAs per batch group)
constexpr int BSL = B_ / BG;  // 16 batch rows per group
}

// Scratch (allocation-free rule: __device__ globals)
__device__ float    g_xw[(size_t)S_ * B_ * H_];   // 256 MB, [t][b][h]
__device__ float    g_hs[(size_t)S_ * B_ * H_];   // 256 MB, [t][b][h]
__device__ unsigned g_cnt[BG * S_];

// ---------------------------------------------------------------------------
__global__ void zero_cnt_kernel() {
    int i = blockIdx.x * blockDim.x + threadIdx.x;
    if (i < BG * S_) g_cnt[i] = 0u;
}

// ---------------------------------------------------------------------------
// C[r][c] = sum_k A'[r][k]*B[c][k] + bias[c].  128x64 tile, 8x4 micro-tile.
// Row r decomposes hi=r/D, lo=r%D; A row offset = (lo*SWAP + hi)*K.
template<int K, int N, int BSTR, int D, int SWAP>
__global__ void __launch_bounds__(256) gemm_bias_kernel(
    const float* __restrict__ A, const float* __restrict__ Bm,
    const float* __restrict__ bias, float* __restrict__ C)
{
    __shared__ float As[16][132];   // +4 pad: STS bank spread
    __shared__ float Bs[16][68];
    const int tid = threadIdx.x;
    const int r0  = blockIdx.y * 128;
    const int c0  = blockIdx.x * 64;

    // A global loads: row = r0 + (tid>>1), two float4 at k = (tid&1)*8 (+0,+4)
    const int arow_l = tid >> 1;
    const int ak     = (tid & 1) * 8;
    const int r  = r0 + arow_l;
    const int hi = r / D, lo = r % D;
    const float* Arow = A + ((size_t)lo * SWAP + hi) * K + ak;

    // B global loads: col = tid>>2, one float4 at k = (tid&3)*4
    const int brow_l = tid >> 2;
    const int bk     = (tid & 3) * 4;
    const float* Brow = Bm + (size_t)(c0 + brow_l) * BSTR + bk;

    const int tr = tid >> 4, tc = tid & 15;   // 8 rows x 4 cols per thread
    float acc[8][4] = {};

    float4 a0 = *reinterpret_cast<const float4*>(Arow);
    float4 a1 = *reinterpret_cast<const float4*>(Arow + 4);
    float4 bv = *reinterpret_cast<const float4*>(Brow);

    for (int kc = 0; kc < K; kc += 16) {
        __syncthreads();
        As[ak+0][arow_l]=a0.x; As[ak+1][arow_l]=a0.y; As[ak+2][arow_l]=a0.z; As[ak+3][arow_l]=a0.w;
        As[ak+4][arow_l]=a1.x; As[ak+5][arow_l]=a1.y; As[ak+6][arow_l]=a1.z; As[ak+7][arow_l]=a1.w;
        Bs[bk+0][brow_l]=bv.x; Bs[bk+1][brow_l]=bv.y; Bs[bk+2][brow_l]=bv.z; Bs[bk+3][brow_l]=bv.w;
        __syncthreads();
        if (kc + 16 < K) {   // register prefetch of next chunk
            a0 = *reinterpret_cast<const float4*>(Arow + kc + 16);
            a1 = *reinterpret_cast<const float4*>(Arow + kc + 16 + 4);
            bv = *reinterpret_cast<const float4*>(Brow + kc + 16);
        }
#pragma unroll
        for (int kk = 0; kk < 16; ++kk) {
            float4 x0 = *reinterpret_cast<const float4*>(&As[kk][tr * 8]);
            float4 x1 = *reinterpret_cast<const float4*>(&As[kk][tr * 8 + 4]);
            float4 y  = *reinterpret_cast<const float4*>(&Bs[kk][tc * 4]);
            float xa[8] = {x0.x,x0.y,x0.z,x0.w,x1.x,x1.y,x1.z,x1.w};
            float yb[4] = {y.x,y.y,y.z,y.w};
#pragma unroll
            for (int i = 0; i < 8; ++i)
#pragma unroll
                for (int j = 0; j < 4; ++j)
                    acc[i][j] = fmaf(xa[i], yb[j], acc[i][j]);
        }
    }

    float4 bsv = *reinterpret_cast<const float4*>(bias + c0 + tc * 4);
#pragma unroll
    for (int i = 0; i < 8; ++i) {
        float4 v;
        v.x = acc[i][0] + bsv.x;
        v.y = acc[i][1] + bsv.y;
        v.z = acc[i][2] + bsv.z;
        v.w = acc[i][3] + bsv.w;
        *reinterpret_cast<float4*>(C + (size_t)(r0 + tr * 8 + i) * N + c0 + tc * 4) = v;
    }
}

// ---------------------------------------------------------------------------
// Multi-value butterfly: merge `HALF*2` accs across lanes at xor-offset O.
// After all 5 levels A[0],A[1] on lane L are full sums of idx 2L, 2L+1.
#define RED_LEVEL(O, HALF)                                                   \
    {                                                                        \
        const bool up_ = (lane & (O)) != 0;                                  \
        _Pragma("unroll")                                                    \
        for (int q_ = 0; q_ < (HALF); ++q_) {                                \
            float s_ = up_ ? A[q_] : A[q_ + (HALF)];                         \
            float r_ = __shfl_xor_sync(0xffffffffu, s_, (O));                \
            A[q_] = (up_ ? A[q_ + (HALF)] : A[q_]) + r_;                     \
        }                                                                    \
    }

// Persistent scan. Grid (JG, BG) = (16, 8), 256 threads.
// CTA (jg,bg): hid slice [jg*32, +32), batch slice [bg*16, +16).
// Warp w owns 4 hid outputs (jbase..jbase+3); lane owns k-slice {lane+32i}.
// Each lane carries ALL 64 accumulators (16 b x 4 j) through the k-loop,
// then one 62-shuffle merge distributes 2 finished outputs to every lane.
__global__ void __launch_bounds__(256, 1) rnn_scan_kernel(const float* __restrict__ W)
{
    const int jg    = blockIdx.x;   // 0..15
    const int bg    = blockIdx.y;   // 0..7
    const int tid   = threadIdx.x;
    const int warp  = tid >> 5;
    const int lane  = tid & 31;
    const int jbase = jg * 32 + warp * 4;

    __shared__ float hsm[BSL * H_];   // 32 KB: h_{t-1} for this batch group

    // Register-resident Wh slice: Wh[j][k] = W[j*(I_+H_) + I_ + k]
    float w[4][16];
#pragma unroll
    for (int jj = 0; jj < 4; ++jj)
#pragma unroll
        for (int i = 0; i < 16; ++i)
            w[jj][i] = W[(size_t)(jbase + jj) * (I_ + H_) + I_ + lane + 32 * i];

    unsigned* cnt = g_cnt + bg * S_;
    const int ob = lane >> 1;                 // batch this lane finalizes
    const int oj = jbase + (lane & 1) * 2;    // first of 2 consecutive j's

    for (int t = 0; t < S_; ++t) {
        float s0 = 0.f, s1 = 0.f;
        if (t > 0) {
            // acquire: all 16 CTAs of this batch group finished t-1
            if (tid == 0) {
                unsigned v;
                do {
                    asm volatile("ld.relaxed.gpu.global.u32 %0, [%1];"
                                 : "=r"(v) : "l"(cnt + (t - 1)) : "memory");
                } while (v < (unsigned)JG);
                asm volatile("fence.acq_rel.gpu;" ::: "memory");
            }
            __syncthreads();
            {   // stage h_{t-1} (32 KB, 8 float4/thread, coalesced)
                const float4* src = reinterpret_cast<const float4*>(
                    g_hs + ((size_t)(t - 1) * B_ + bg * BSL) * H_);
                float4* dst = reinterpret_cast<float4*>(hsm);
#pragma unroll
                for (int i = 0; i < (BSL * H_ / 4) / 256; ++i)
                    dst[tid + 256 * i] = src[tid + 256 * i];
            }
            __syncthreads();

            float A[64];   // A[b*4+jj]
#pragma unroll
            for (int q = 0; q < 64; ++q) A[q] = 0.f;
#pragma unroll
            for (int i = 0; i < 16; ++i) {
                const int kofs = lane + 32 * i;
#pragma unroll
                for (int b = 0; b < 16; ++b) {
                    float hv = hsm[b * H_ + kofs];     // conflict-free LDS
#pragma unroll
                    for (int jj = 0; jj < 4; ++jj)
                        A[b * 4 + jj] = fmaf(hv, w[jj][i], A[b * 4 + jj]);
                }
            }
            RED_LEVEL(16, 32)
            RED_LEVEL(8, 16)
            RED_LEVEL(4, 8)
            RED_LEVEL(2, 4)
            RED_LEVEL(1, 2)
            s0 = A[0];   // sum for (ob, oj)
            s1 = A[1];   // sum for (ob, oj+1)
        }

        const size_t rowoff = ((size_t)t * B_ + bg * BSL + ob) * H_ + oj;
        float2 xv = *reinterpret_cast<const float2*>(g_xw + rowoff);
        float2 hv2;
        hv2.x = tanhf(xv.x + s0);
        hv2.y = tanhf(xv.y + s1);
        *reinterpret_cast<float2*>(g_hs + rowoff) = hv2;

        __syncthreads();
        if (tid == 0) {   // release: publish our hid slice of h_t
            asm volatile("fence.acq_rel.gpu;" ::: "memory");
            atomicAdd(cnt + t, 1u);
        }
    }
}

// ---------------------------------------------------------------------------
__global__ void copy_hlast_kernel(float* __restrict__ out) {
    int i = blockIdx.x * blockDim.x + threadIdx.x;
    out[i] = g_hs[(size_t)(S_ - 1) * B_ * H_ + i];   // [b][h] slice, contiguous
}

// ---------------------------------------------------------------------------
extern "C" void kernel_launch(void* const* d_in, const int* in_sizes, int n_in,
                              void* d_out, int out_size)
{
    const float* x  = (const float*)d_in[0];   // [128,1024,256]
    const float* Wi = (const float*)d_in[1];   // [512,768]
    const float* bi = (const float*)d_in[2];   // [512]
    const float* Wo = (const float*)d_in[3];   // [256,512]
    const float* bo = (const float*)d_in[4];   // [256]
    float* out = (float*)d_out;

    float* xw_d = nullptr;
    float* hs_d = nullptr;
    cudaGetSymbolAddress((void**)&xw_d, g_xw);
    cudaGetSymbolAddress((void**)&hs_d, g_hs);

    // reset sync counters (graph replays must be deterministic)
    zero_cnt_kernel<<<(BG * S_ + 255) / 256, 256>>>();

    // Phase 1: xW[t][b][h]  (r = t*128+b, A row = (b*S_+t)*I_)
    {
        dim3 g(H_ / 64, (S_ * B_) / 128);
        gemm_bias_kernel<I_, H_, I_ + H_, B_, S_><<<g, 256>>>(x, Wi, bi, xw_d);
    }

    // Phase 2: sequential scan (persistent, 128 co-resident CTAs)
    rnn_scan_kernel<<<dim3(JG, BG), 256>>>(Wi);

    // Phase 3: outputs[b][s][o]  (r = b*S_+s, A row = (s*B_+b)*H_)
    {
        dim3 g(O_ / 64, (B_ * S_) / 128);
        gemm_bias_kernel<H_, O_, H_, S_, B_><<<g, 256>>>(hs_d, Wo, bo, out);
    }

    // h_last
    if (out_size >= B_ * S_ * O_ + B_ * H_)
        copy_hlast_kernel<<<(B_ * H_) / 256, 256>>>(out + (size_t)B_ * S_ * O_);
}